// round 1
// baseline (speedup 1.0000x reference)
#include <cuda_runtime.h>
#include <math.h>

#define NB 4
#define C2C 128
#define HH 128
#define WW 128
#define PP (HH*WW)          // 16384
#define GKC 40

// ---------------- scratch (device globals; no allocation allowed) -----------
__device__ float g_h[(size_t)NB*256*PP];       // proj_in output (x1 | x2)
__device__ float g_mid[(size_t)NB*64*PP];      // cb hidden
__device__ float g_xconv[(size_t)NB*C2C*PP];   // x_conv
__device__ float g_dw[(size_t)NB*C2C*PP];      // depthwise scratch (h then v)
__device__ float g_k[(size_t)NB*GKC*PP];       // kh then kv
__device__ float g_attnh[(size_t)NB*C2C*PP];
__device__ float g_attn[(size_t)NB*C2C*PP];
__device__ float g_cat[(size_t)NB*256*PP];
__device__ float g_atmean[NB*C2C];
__device__ float g_xcmean[NB*PP];
__device__ float g_ssig[NB*PP];
__device__ float g_csig[NB*C2C];

// ---------------- generic tiled SGEMM: C[b] = act(A * B[b] + bias) ----------
// A: [M,K] row-major, B: [K,N] row-major per batch, C: [M,N] per batch.
// ACT: 0 none, 1 relu, 2 tanh
template<int ACT>
__global__ void gemm64(const float* __restrict__ A, const float* __restrict__ bias,
                       const float* __restrict__ Bm, float* __restrict__ Cm,
                       int M, int K, int N, size_t sB, size_t sC)
{
    __shared__ float As[16][64];
    __shared__ float Bs[16][64];
    const float* Bp = Bm + (size_t)blockIdx.z * sB;
    float*       Cp = Cm + (size_t)blockIdx.z * sC;
    const int m0 = blockIdx.y * 64, n0 = blockIdx.x * 64;
    const int tid = threadIdx.x;
    const int tx = tid & 15, ty = tid >> 4;
    const int ar = tid >> 2;            // 0..63  (A row in tile)
    const int ac = (tid & 3) << 2;      // 0,4,8,12 (A col group)
    const int br = tid >> 4;            // 0..15  (B row in tile)
    const int bc = (tid & 15) << 2;     // 0..60  (B col group)

    float acc[4][4];
#pragma unroll
    for (int i = 0; i < 4; i++)
#pragma unroll
        for (int j = 0; j < 4; j++) acc[i][j] = 0.f;

    for (int k0 = 0; k0 < K; k0 += 16) {
        float4 av = make_float4(0.f, 0.f, 0.f, 0.f);
        if (m0 + ar < M)
            av = *(const float4*)(A + (size_t)(m0 + ar) * K + k0 + ac);
        As[ac + 0][ar] = av.x; As[ac + 1][ar] = av.y;
        As[ac + 2][ar] = av.z; As[ac + 3][ar] = av.w;
        *(float4*)&Bs[br][bc] = *(const float4*)(Bp + (size_t)(k0 + br) * N + n0 + bc);
        __syncthreads();
#pragma unroll
        for (int kk = 0; kk < 16; kk++) {
            float4 a4 = *(const float4*)&As[kk][ty << 2];
            float4 b4 = *(const float4*)&Bs[kk][tx << 2];
            float a[4] = {a4.x, a4.y, a4.z, a4.w};
            float b[4] = {b4.x, b4.y, b4.z, b4.w};
#pragma unroll
            for (int i = 0; i < 4; i++)
#pragma unroll
                for (int j = 0; j < 4; j++) acc[i][j] = fmaf(a[i], b[j], acc[i][j]);
        }
        __syncthreads();
    }

#pragma unroll
    for (int i = 0; i < 4; i++) {
        int m = m0 + (ty << 2) + i;
        if (m >= M) continue;
        float bv = bias[m];
        float v0 = acc[i][0] + bv, v1 = acc[i][1] + bv;
        float v2 = acc[i][2] + bv, v3 = acc[i][3] + bv;
        if (ACT == 1) { v0 = fmaxf(v0, 0.f); v1 = fmaxf(v1, 0.f); v2 = fmaxf(v2, 0.f); v3 = fmaxf(v3, 0.f); }
        if (ACT == 2) { v0 = tanhf(v0); v1 = tanhf(v1); v2 = tanhf(v2); v3 = tanhf(v3); }
        *(float4*)(Cp + (size_t)m * N + n0 + (tx << 2)) = make_float4(v0, v1, v2, v3);
    }
}

// ---------------- depthwise 1x7 (horizontal), zero pad, cross-correlation ---
__global__ void dwconv_h(const float* __restrict__ x, size_t sX,
                         const float* __restrict__ w7, const float* __restrict__ bias,
                         float* __restrict__ y)
{
    int idx = blockIdx.x * blockDim.x + threadIdx.x;
    if (idx >= NB * C2C * PP) return;
    int p = idx % PP;
    int c = (idx / PP) % C2C;
    int b = idx / (PP * C2C);
    int w = p % WW;
    const float* xr = x + (size_t)b * sX + (size_t)c * PP + (p - w);
    float s = bias[c];
#pragma unroll
    for (int j = 0; j < 7; j++) {
        int wj = w + j - 3;
        if (wj >= 0 && wj < WW) s = fmaf(xr[wj], w7[c * 7 + j], s);
    }
    y[idx] = s;
}

// ---------------- depthwise 7x1 (vertical) ----------------------------------
__global__ void dwconv_v(const float* __restrict__ x, size_t sX,
                         const float* __restrict__ w7, const float* __restrict__ bias,
                         float* __restrict__ y)
{
    int idx = blockIdx.x * blockDim.x + threadIdx.x;
    if (idx >= NB * C2C * PP) return;
    int p = idx % PP;
    int c = (idx / PP) % C2C;
    int b = idx / (PP * C2C);
    int h = p / WW, w = p % WW;
    const float* xc = x + (size_t)b * sX + (size_t)c * PP;
    float s = bias[c];
#pragma unroll
    for (int j = 0; j < 7; j++) {
        int hj = h + j - 3;
        if (hj >= 0 && hj < HH) s = fmaf(xc[hj * WW + w], w7[c * 7 + j], s);
    }
    y[idx] = s;
}

// ---------------- focal-ish spatial attention, horizontal -------------------
// taps: [(x[-3]+x[-2])/2, x[-1], x[0], x[+1], (x[+2]+x[+3])/2] dot kern[b,g*5+k,h,w]
__global__ void fsa_h(const float* __restrict__ x, size_t sX,
                      const float* __restrict__ kern, float* __restrict__ out)
{
    int idx = blockIdx.x * blockDim.x + threadIdx.x;
    if (idx >= NB * C2C * PP) return;
    int p = idx % PP;
    int c = (idx / PP) % C2C;
    int b = idx / (PP * C2C);
    int w = p % WW;
    const float* xr = x + (size_t)b * sX + (size_t)c * PP + (p - w);
    float xm3 = (w >= 3) ? xr[w - 3] : 0.f;
    float xm2 = (w >= 2) ? xr[w - 2] : 0.f;
    float xm1 = (w >= 1) ? xr[w - 1] : 0.f;
    float x0  = xr[w];
    float xp1 = (w + 1 < WW) ? xr[w + 1] : 0.f;
    float xp2 = (w + 2 < WW) ? xr[w + 2] : 0.f;
    float xp3 = (w + 3 < WW) ? xr[w + 3] : 0.f;
    float t0 = (xm3 + xm2) * 0.5f, t4 = (xp2 + xp3) * 0.5f;
    const float* kb = kern + ((size_t)b * GKC + (size_t)(c >> 4) * 5) * PP + p;
    float s = t0 * kb[0];
    s = fmaf(xm1, kb[PP],     s);
    s = fmaf(x0,  kb[2 * PP], s);
    s = fmaf(xp1, kb[3 * PP], s);
    s = fmaf(t4,  kb[4 * PP], s);
    out[idx] = s;
}

// ---------------- focal-ish spatial attention, vertical ---------------------
__global__ void fsa_v(const float* __restrict__ x, size_t sX,
                      const float* __restrict__ kern, float* __restrict__ out)
{
    int idx = blockIdx.x * blockDim.x + threadIdx.x;
    if (idx >= NB * C2C * PP) return;
    int p = idx % PP;
    int c = (idx / PP) % C2C;
    int b = idx / (PP * C2C);
    int h = p / WW, w = p % WW;
    const float* xc = x + (size_t)b * sX + (size_t)c * PP;
    float xm3 = (h >= 3) ? xc[(h - 3) * WW + w] : 0.f;
    float xm2 = (h >= 2) ? xc[(h - 2) * WW + w] : 0.f;
    float xm1 = (h >= 1) ? xc[(h - 1) * WW + w] : 0.f;
    float x0  = xc[h * WW + w];
    float xp1 = (h + 1 < HH) ? xc[(h + 1) * WW + w] : 0.f;
    float xp2 = (h + 2 < HH) ? xc[(h + 2) * WW + w] : 0.f;
    float xp3 = (h + 3 < HH) ? xc[(h + 3) * WW + w] : 0.f;
    float t0 = (xm3 + xm2) * 0.5f, t4 = (xp2 + xp3) * 0.5f;
    const float* kb = kern + ((size_t)b * GKC + (size_t)(c >> 4) * 5) * PP + p;
    float s = t0 * kb[0];
    s = fmaf(xm1, kb[PP],     s);
    s = fmaf(x0,  kb[2 * PP], s);
    s = fmaf(xp1, kb[3 * PP], s);
    s = fmaf(t4,  kb[4 * PP], s);
    out[idx] = s;
}

// ---------------- reductions / gating ---------------------------------------
__global__ void reduce_mean_p(const float* __restrict__ x, float* __restrict__ out)
{
    // one block per (b,c): mean over P
    int bc = blockIdx.x;
    const float* xr = x + (size_t)bc * PP;
    float s = 0.f;
    for (int i = threadIdx.x; i < PP; i += 256) s += xr[i];
    __shared__ float sm[256];
    sm[threadIdx.x] = s; __syncthreads();
    for (int st = 128; st > 0; st >>= 1) {
        if (threadIdx.x < st) sm[threadIdx.x] += sm[threadIdx.x + st];
        __syncthreads();
    }
    if (threadIdx.x == 0) out[bc] = sm[0] * (1.f / PP);
}

__global__ void mean_c(const float* __restrict__ x, float* __restrict__ out)
{
    int idx = blockIdx.x * 256 + threadIdx.x;     // NB*PP
    if (idx >= NB * PP) return;
    int p = idx % PP, b = idx / PP;
    const float* xr = x + (size_t)b * C2C * PP + p;
    float s = 0.f;
#pragma unroll 8
    for (int c = 0; c < C2C; c++) s += xr[(size_t)c * PP];
    out[idx] = s * (1.f / C2C);
}

__global__ void ssig_kernel(const float* __restrict__ xconv,
                            const float* __restrict__ atmean,
                            float* __restrict__ out)
{
    int b = blockIdx.y;
    int p = blockIdx.x * 256 + threadIdx.x;
    __shared__ float am[C2C];
    if (threadIdx.x < C2C) am[threadIdx.x] = atmean[b * C2C + threadIdx.x];
    __syncthreads();
    const float* xr = xconv + (size_t)b * C2C * PP + p;
    float s = 0.f;
#pragma unroll 8
    for (int c = 0; c < C2C; c++) s = fmaf(am[c], xr[(size_t)c * PP], s);
    s *= (1.f / C2C);
    out[b * PP + p] = 1.f / (1.f + expf(-s));
}

__global__ void csig_kernel(const float* __restrict__ attn,
                            const float* __restrict__ xcmean,
                            float* __restrict__ out)
{
    int bc = blockIdx.x;           // NB*C2C blocks
    int b = bc / C2C;
    const float* ar = attn + (size_t)bc * PP;
    const float* xm = xcmean + (size_t)b * PP;
    float s = 0.f;
    for (int i = threadIdx.x; i < PP; i += 256) s = fmaf(ar[i], xm[i], s);
    __shared__ float sm[256];
    sm[threadIdx.x] = s; __syncthreads();
    for (int st = 128; st > 0; st >>= 1) {
        if (threadIdx.x < st) sm[threadIdx.x] += sm[threadIdx.x + st];
        __syncthreads();
    }
    if (threadIdx.x == 0) {
        float v = sm[0] * (1.f / PP);
        out[bc] = 1.f / (1.f + expf(-v));
    }
}

__global__ void cat_kernel(const float* __restrict__ xconv, const float* __restrict__ attn,
                           const float* __restrict__ ssig, const float* __restrict__ csig,
                           float* __restrict__ out)
{
    int idx = blockIdx.x * 256 + threadIdx.x;     // NB*256*PP
    if (idx >= NB * 256 * PP) return;
    int p = idx % PP;
    int o = (idx / PP) & 255;
    int b = idx / (PP * 256);
    float v;
    if (o < C2C)
        v = ssig[b * PP + p] * xconv[((size_t)b * C2C + o) * PP + p];
    else
        v = csig[b * C2C + (o - C2C)] * attn[((size_t)b * C2C + (o - C2C)) * PP + p];
    out[idx] = v;
}

// ---------------- host orchestration ----------------------------------------
extern "C" void kernel_launch(void* const* d_in, const int* in_sizes, int n_in,
                              void* d_out, int out_size)
{
    const float* x         = (const float*)d_in[0];
    const float* proj_in_w = (const float*)d_in[1];
    const float* proj_in_b = (const float*)d_in[2];
    const float* hk_dw_w   = (const float*)d_in[3];
    const float* hk_dw_b   = (const float*)d_in[4];
    const float* hk_pw_w   = (const float*)d_in[5];
    const float* hk_pw_b   = (const float*)d_in[6];
    const float* vk_dw_w   = (const float*)d_in[7];
    const float* vk_dw_b   = (const float*)d_in[8];
    const float* vk_pw_w   = (const float*)d_in[9];
    const float* vk_pw_b   = (const float*)d_in[10];
    const float* cb_w1     = (const float*)d_in[11];
    const float* cb_b1     = (const float*)d_in[12];
    const float* cb_w2     = (const float*)d_in[13];
    const float* cb_b2     = (const float*)d_in[14];
    const float* proj_out_w= (const float*)d_in[15];
    const float* proj_out_b= (const float*)d_in[16];
    float* out = (float*)d_out;

    float *p_h, *p_mid, *p_xconv, *p_dw, *p_k, *p_attnh, *p_attn, *p_cat;
    float *p_atmean, *p_xcmean, *p_ssig, *p_csig;
    cudaGetSymbolAddress((void**)&p_h,      g_h);
    cudaGetSymbolAddress((void**)&p_mid,    g_mid);
    cudaGetSymbolAddress((void**)&p_xconv,  g_xconv);
    cudaGetSymbolAddress((void**)&p_dw,     g_dw);
    cudaGetSymbolAddress((void**)&p_k,      g_k);
    cudaGetSymbolAddress((void**)&p_attnh,  g_attnh);
    cudaGetSymbolAddress((void**)&p_attn,   g_attn);
    cudaGetSymbolAddress((void**)&p_cat,    g_cat);
    cudaGetSymbolAddress((void**)&p_atmean, g_atmean);
    cudaGetSymbolAddress((void**)&p_xcmean, g_xcmean);
    cudaGetSymbolAddress((void**)&p_ssig,   g_ssig);
    cudaGetSymbolAddress((void**)&p_csig,   g_csig);

    const int N = PP;
    const int elemBlocks = (NB * C2C * PP) / 256;   // 32768

    // 1) proj_in: h = x @ W^T + b       (M=256,K=256)
    gemm64<0><<<dim3(N/64, 4, NB), 256>>>(proj_in_w, proj_in_b, x, p_h,
                                          256, 256, N, (size_t)256*PP, (size_t)256*PP);
    // 2) cb hidden = relu(x1 @ cb_w1^T) (M=64,K=128)   x1 = g_h[:, :128]
    gemm64<1><<<dim3(N/64, 1, NB), 256>>>(cb_w1, cb_b1, p_h, p_mid,
                                          64, 128, N, (size_t)256*PP, (size_t)64*PP);
    // 3) x_conv = mid @ cb_w2^T         (M=128,K=64)
    gemm64<0><<<dim3(N/64, 2, NB), 256>>>(cb_w2, cb_b2, p_mid, p_xconv,
                                          128, 64, N, (size_t)64*PP, (size_t)C2C*PP);
    // 4) horizontal depthwise on x2 = g_h[:, 128:]
    dwconv_h<<<elemBlocks, 256>>>(p_h + (size_t)C2C*PP, (size_t)256*PP, hk_dw_w, hk_dw_b, p_dw);
    // 5) kh = tanh(dwh @ hk_pw^T)       (M=40,K=128)
    gemm64<2><<<dim3(N/64, 1, NB), 256>>>(hk_pw_w, hk_pw_b, p_dw, p_k,
                                          GKC, 128, N, (size_t)C2C*PP, (size_t)GKC*PP);
    // 6) attn_h = fsa(x2, kh, axis=w)
    fsa_h<<<elemBlocks, 256>>>(p_h + (size_t)C2C*PP, (size_t)256*PP, p_k, p_attnh);
    // 7) vertical depthwise on attn_h
    dwconv_v<<<elemBlocks, 256>>>(p_attnh, (size_t)C2C*PP, vk_dw_w, vk_dw_b, p_dw);
    // 8) kv = tanh(dwv @ vk_pw^T)
    gemm64<2><<<dim3(N/64, 1, NB), 256>>>(vk_pw_w, vk_pw_b, p_dw, p_k,
                                          GKC, 128, N, (size_t)C2C*PP, (size_t)GKC*PP);
    // 9) attn = fsa(attn_h, kv, axis=h)
    fsa_v<<<elemBlocks, 256>>>(p_attnh, (size_t)C2C*PP, p_k, p_attn);
    // 10) at_mean[b,c]
    reduce_mean_p<<<NB*C2C, 256>>>(p_attn, p_atmean);
    // 11) xc_mean[b,p]
    mean_c<<<(NB*PP)/256, 256>>>(p_xconv, p_xcmean);
    // 12) s_sig[b,p]
    ssig_kernel<<<dim3(PP/256, NB), 256>>>(p_xconv, p_atmean, p_ssig);
    // 13) c_sig[b,c]
    csig_kernel<<<NB*C2C, 256>>>(p_attn, p_xcmean, p_csig);
    // 14) concat with gates
    cat_kernel<<<(NB*256*PP)/256, 256>>>(p_xconv, p_attn, p_ssig, p_csig, p_cat);
    // 15) proj_out -> d_out
    gemm64<0><<<dim3(N/64, 4, NB), 256>>>(proj_out_w, proj_out_b, p_cat, out,
                                          256, 256, N, (size_t)256*PP, (size_t)256*PP);
}

// round 2
// speedup vs baseline: 1.2677x; 1.2677x over previous
#include <cuda_runtime.h>
#include <math.h>
#include <stdint.h>

#define NB 4
#define C2C 128
#define HH 128
#define WW 128
#define PP (HH*WW)          // 16384
#define GKC 40

// ---------------- scratch (device globals; no allocation allowed) -----------
__device__ float g_h[(size_t)NB*256*PP];       // proj_in output (x1 | x2)
__device__ float g_mid[(size_t)NB*64*PP];      // cb hidden
__device__ float g_xconv[(size_t)NB*C2C*PP];   // x_conv
__device__ float g_dw[(size_t)NB*C2C*PP];      // depthwise scratch (h then v)
__device__ float g_k[(size_t)NB*GKC*PP];       // kh then kv
__device__ float g_attnh[(size_t)NB*C2C*PP];
__device__ float g_attn[(size_t)NB*C2C*PP];
__device__ float g_cat[(size_t)NB*256*PP];
__device__ float g_atmean[NB*C2C];
__device__ float g_xcmean[NB*PP];
__device__ float g_ssig[NB*PP];
__device__ float g_csig[NB*C2C];

// ---------------- tf32 helpers ----------------------------------------------
__device__ __forceinline__ uint32_t f2tf32(float x) {
    uint32_t u;
    asm("cvt.rna.tf32.f32 %0, %1;" : "=r"(u) : "f"(x));
    return u;
}

__device__ __forceinline__ void mma_tf32(float c[4], const uint32_t a[4], const uint32_t b[2]) {
    asm volatile(
        "mma.sync.aligned.m16n8k8.row.col.f32.tf32.tf32.f32 "
        "{%0,%1,%2,%3}, {%4,%5,%6,%7}, {%8,%9}, {%0,%1,%2,%3};\n"
        : "+f"(c[0]), "+f"(c[1]), "+f"(c[2]), "+f"(c[3])
        : "r"(a[0]), "r"(a[1]), "r"(a[2]), "r"(a[3]), "r"(b[0]), "r"(b[1]));
}

// ---------------- tf32 tensor-core GEMM: C[b] = act(A * B[b] + bias) --------
// A: [M,K] row-major weights. B: [K,N] row-major per batch. C: [M,N].
// Block tile 64(M) x 128(N), BK=32. 8 warps: 2(m) x 4(n), warp tile 32x32.
// ACT: 0 none, 1 relu, 2 tanh. K % 32 == 0, N % 128 == 0 required.
template<int ACT>
__global__ __launch_bounds__(256) void gemm_tc(
    const float* __restrict__ A, const float* __restrict__ bias,
    const float* __restrict__ Bm, float* __restrict__ Cm,
    int M, int K, int N, size_t sB, size_t sC)
{
    __shared__ uint32_t As[64][33];        // [m][k], pad to kill conflicts
    __shared__ uint32_t Bs[32][128];       // [k][n]

    const float* Bp = Bm + (size_t)blockIdx.z * sB;
    float*       Cp = Cm + (size_t)blockIdx.z * sC;
    const int m0 = blockIdx.y * 64, n0 = blockIdx.x * 128;
    const int tid  = threadIdx.x;
    const int lane = tid & 31, warp = tid >> 5;
    const int wm = warp & 1, wn = warp >> 1;      // 2 x 4 warp grid
    const int g = lane >> 2, tig = lane & 3;

    float acc[2][4][4];
#pragma unroll
    for (int mi = 0; mi < 2; mi++)
#pragma unroll
        for (int ni = 0; ni < 4; ni++)
#pragma unroll
            for (int r = 0; r < 4; r++) acc[mi][ni][r] = 0.f;

    // A loader: thread covers rows (tid>>3) and (tid>>3)+32, col-group tid&7
    const int arow = tid >> 3, ac4 = (tid & 7) << 2;
    // B loader: rows (tid>>5)+8*i, col-group tid&31
    const int brow = tid >> 5, bc4 = (tid & 31) << 2;

    for (int k0 = 0; k0 < K; k0 += 32) {
#pragma unroll
        for (int i = 0; i < 2; i++) {
            int r = arow + i * 32;
            float4 v = make_float4(0.f, 0.f, 0.f, 0.f);
            if (m0 + r < M)
                v = *(const float4*)(A + (size_t)(m0 + r) * K + k0 + ac4);
            As[r][ac4 + 0] = f2tf32(v.x);
            As[r][ac4 + 1] = f2tf32(v.y);
            As[r][ac4 + 2] = f2tf32(v.z);
            As[r][ac4 + 3] = f2tf32(v.w);
        }
#pragma unroll
        for (int i = 0; i < 4; i++) {
            int r = brow + i * 8;
            float4 v = *(const float4*)(Bp + (size_t)(k0 + r) * N + n0 + bc4);
            Bs[r][bc4 + 0] = f2tf32(v.x);
            Bs[r][bc4 + 1] = f2tf32(v.y);
            Bs[r][bc4 + 2] = f2tf32(v.z);
            Bs[r][bc4 + 3] = f2tf32(v.w);
        }
        __syncthreads();

#pragma unroll
        for (int kk = 0; kk < 4; kk++) {
            const int kb = kk * 8;
            uint32_t a[2][4];
#pragma unroll
            for (int mi = 0; mi < 2; mi++) {
                int br = wm * 32 + mi * 16 + g;
                a[mi][0] = As[br][kb + tig];
                a[mi][1] = As[br + 8][kb + tig];
                a[mi][2] = As[br][kb + tig + 4];
                a[mi][3] = As[br + 8][kb + tig + 4];
            }
            uint32_t b[4][2];
#pragma unroll
            for (int ni = 0; ni < 4; ni++) {
                int col = wn * 32 + ni * 8 + g;
                b[ni][0] = Bs[kb + tig][col];
                b[ni][1] = Bs[kb + tig + 4][col];
            }
#pragma unroll
            for (int mi = 0; mi < 2; mi++)
#pragma unroll
                for (int ni = 0; ni < 4; ni++)
                    mma_tf32(acc[mi][ni], a[mi], b[ni]);
        }
        __syncthreads();
    }

    // epilogue
#pragma unroll
    for (int mi = 0; mi < 2; mi++) {
        int row_lo = m0 + wm * 32 + mi * 16 + g;
        int row_hi = row_lo + 8;
        float blo = (row_lo < M) ? bias[row_lo] : 0.f;
        float bhi = (row_hi < M) ? bias[row_hi] : 0.f;
#pragma unroll
        for (int ni = 0; ni < 4; ni++) {
            int col = n0 + wn * 32 + ni * 8 + tig * 2;
            float v0 = acc[mi][ni][0] + blo, v1 = acc[mi][ni][1] + blo;
            float v2 = acc[mi][ni][2] + bhi, v3 = acc[mi][ni][3] + bhi;
            if (ACT == 1) { v0 = fmaxf(v0, 0.f); v1 = fmaxf(v1, 0.f);
                            v2 = fmaxf(v2, 0.f); v3 = fmaxf(v3, 0.f); }
            if (ACT == 2) { v0 = tanhf(v0); v1 = tanhf(v1);
                            v2 = tanhf(v2); v3 = tanhf(v3); }
            if (row_lo < M) *(float2*)(Cp + (size_t)row_lo * N + col) = make_float2(v0, v1);
            if (row_hi < M) *(float2*)(Cp + (size_t)row_hi * N + col) = make_float2(v2, v3);
        }
    }
}

// ---------------- depthwise 1x7 (horizontal), zero pad ----------------------
__global__ void dwconv_h(const float* __restrict__ x, size_t sX,
                         const float* __restrict__ w7, const float* __restrict__ bias,
                         float* __restrict__ y)
{
    int idx = blockIdx.x * blockDim.x + threadIdx.x;
    if (idx >= NB * C2C * PP) return;
    int p = idx % PP;
    int c = (idx / PP) % C2C;
    int b = idx / (PP * C2C);
    int w = p % WW;
    const float* xr = x + (size_t)b * sX + (size_t)c * PP + (p - w);
    float s = bias[c];
#pragma unroll
    for (int j = 0; j < 7; j++) {
        int wj = w + j - 3;
        if (wj >= 0 && wj < WW) s = fmaf(xr[wj], w7[c * 7 + j], s);
    }
    y[idx] = s;
}

// ---------------- depthwise 7x1 (vertical) ----------------------------------
__global__ void dwconv_v(const float* __restrict__ x, size_t sX,
                         const float* __restrict__ w7, const float* __restrict__ bias,
                         float* __restrict__ y)
{
    int idx = blockIdx.x * blockDim.x + threadIdx.x;
    if (idx >= NB * C2C * PP) return;
    int p = idx % PP;
    int c = (idx / PP) % C2C;
    int b = idx / (PP * C2C);
    int h = p / WW, w = p % WW;
    const float* xc = x + (size_t)b * sX + (size_t)c * PP;
    float s = bias[c];
#pragma unroll
    for (int j = 0; j < 7; j++) {
        int hj = h + j - 3;
        if (hj >= 0 && hj < HH) s = fmaf(xc[hj * WW + w], w7[c * 7 + j], s);
    }
    y[idx] = s;
}

// ---------------- FSA horizontal ---------------------------------------------
__global__ void fsa_h(const float* __restrict__ x, size_t sX,
                      const float* __restrict__ kern, float* __restrict__ out)
{
    int idx = blockIdx.x * blockDim.x + threadIdx.x;
    if (idx >= NB * C2C * PP) return;
    int p = idx % PP;
    int c = (idx / PP) % C2C;
    int b = idx / (PP * C2C);
    int w = p % WW;
    const float* xr = x + (size_t)b * sX + (size_t)c * PP + (p - w);
    float xm3 = (w >= 3) ? xr[w - 3] : 0.f;
    float xm2 = (w >= 2) ? xr[w - 2] : 0.f;
    float xm1 = (w >= 1) ? xr[w - 1] : 0.f;
    float x0  = xr[w];
    float xp1 = (w + 1 < WW) ? xr[w + 1] : 0.f;
    float xp2 = (w + 2 < WW) ? xr[w + 2] : 0.f;
    float xp3 = (w + 3 < WW) ? xr[w + 3] : 0.f;
    float t0 = (xm3 + xm2) * 0.5f, t4 = (xp2 + xp3) * 0.5f;
    const float* kb = kern + ((size_t)b * GKC + (size_t)(c >> 4) * 5) * PP + p;
    float s = t0 * kb[0];
    s = fmaf(xm1, kb[PP],     s);
    s = fmaf(x0,  kb[2 * PP], s);
    s = fmaf(xp1, kb[3 * PP], s);
    s = fmaf(t4,  kb[4 * PP], s);
    out[idx] = s;
}

// ---------------- FSA vertical ------------------------------------------------
__global__ void fsa_v(const float* __restrict__ x, size_t sX,
                      const float* __restrict__ kern, float* __restrict__ out)
{
    int idx = blockIdx.x * blockDim.x + threadIdx.x;
    if (idx >= NB * C2C * PP) return;
    int p = idx % PP;
    int c = (idx / PP) % C2C;
    int b = idx / (PP * C2C);
    int h = p / WW, w = p % WW;
    const float* xc = x + (size_t)b * sX + (size_t)c * PP;
    float xm3 = (h >= 3) ? xc[(h - 3) * WW + w] : 0.f;
    float xm2 = (h >= 2) ? xc[(h - 2) * WW + w] : 0.f;
    float xm1 = (h >= 1) ? xc[(h - 1) * WW + w] : 0.f;
    float x0  = xc[h * WW + w];
    float xp1 = (h + 1 < HH) ? xc[(h + 1) * WW + w] : 0.f;
    float xp2 = (h + 2 < HH) ? xc[(h + 2) * WW + w] : 0.f;
    float xp3 = (h + 3 < HH) ? xc[(h + 3) * WW + w] : 0.f;
    float t0 = (xm3 + xm2) * 0.5f, t4 = (xp2 + xp3) * 0.5f;
    const float* kb = kern + ((size_t)b * GKC + (size_t)(c >> 4) * 5) * PP + p;
    float s = t0 * kb[0];
    s = fmaf(xm1, kb[PP],     s);
    s = fmaf(x0,  kb[2 * PP], s);
    s = fmaf(xp1, kb[3 * PP], s);
    s = fmaf(t4,  kb[4 * PP], s);
    out[idx] = s;
}

// ---------------- reductions / gating ---------------------------------------
__global__ void reduce_mean_p(const float* __restrict__ x, float* __restrict__ out)
{
    int bc = blockIdx.x;
    const float* xr = x + (size_t)bc * PP;
    float s = 0.f;
    for (int i = threadIdx.x; i < PP; i += 256) s += xr[i];
    __shared__ float sm[256];
    sm[threadIdx.x] = s; __syncthreads();
    for (int st = 128; st > 0; st >>= 1) {
        if (threadIdx.x < st) sm[threadIdx.x] += sm[threadIdx.x + st];
        __syncthreads();
    }
    if (threadIdx.x == 0) out[bc] = sm[0] * (1.f / PP);
}

__global__ void mean_c(const float* __restrict__ x, float* __restrict__ out)
{
    int idx = blockIdx.x * 256 + threadIdx.x;     // NB*PP
    if (idx >= NB * PP) return;
    int p = idx % PP, b = idx / PP;
    const float* xr = x + (size_t)b * C2C * PP + p;
    float s = 0.f;
#pragma unroll 8
    for (int c = 0; c < C2C; c++) s += xr[(size_t)c * PP];
    out[idx] = s * (1.f / C2C);
}

__global__ void ssig_kernel(const float* __restrict__ xconv,
                            const float* __restrict__ atmean,
                            float* __restrict__ out)
{
    int b = blockIdx.y;
    int p = blockIdx.x * 256 + threadIdx.x;
    __shared__ float am[C2C];
    if (threadIdx.x < C2C) am[threadIdx.x] = atmean[b * C2C + threadIdx.x];
    __syncthreads();
    const float* xr = xconv + (size_t)b * C2C * PP + p;
    float s = 0.f;
#pragma unroll 8
    for (int c = 0; c < C2C; c++) s = fmaf(am[c], xr[(size_t)c * PP], s);
    s *= (1.f / C2C);
    out[b * PP + p] = 1.f / (1.f + expf(-s));
}

__global__ void csig_kernel(const float* __restrict__ attn,
                            const float* __restrict__ xcmean,
                            float* __restrict__ out)
{
    int bc = blockIdx.x;
    int b = bc / C2C;
    const float* ar = attn + (size_t)bc * PP;
    const float* xm = xcmean + (size_t)b * PP;
    float s = 0.f;
    for (int i = threadIdx.x; i < PP; i += 256) s = fmaf(ar[i], xm[i], s);
    __shared__ float sm[256];
    sm[threadIdx.x] = s; __syncthreads();
    for (int st = 128; st > 0; st >>= 1) {
        if (threadIdx.x < st) sm[threadIdx.x] += sm[threadIdx.x + st];
        __syncthreads();
    }
    if (threadIdx.x == 0) {
        float v = sm[0] * (1.f / PP);
        out[bc] = 1.f / (1.f + expf(-v));
    }
}

__global__ void cat_kernel(const float* __restrict__ xconv, const float* __restrict__ attn,
                           const float* __restrict__ ssig, const float* __restrict__ csig,
                           float* __restrict__ out)
{
    int idx = blockIdx.x * 256 + threadIdx.x;
    if (idx >= NB * 256 * PP) return;
    int p = idx % PP;
    int o = (idx / PP) & 255;
    int b = idx / (PP * 256);
    float v;
    if (o < C2C)
        v = ssig[b * PP + p] * xconv[((size_t)b * C2C + o) * PP + p];
    else
        v = csig[b * C2C + (o - C2C)] * attn[((size_t)b * C2C + (o - C2C)) * PP + p];
    out[idx] = v;
}

// ---------------- host orchestration ----------------------------------------
extern "C" void kernel_launch(void* const* d_in, const int* in_sizes, int n_in,
                              void* d_out, int out_size)
{
    const float* x         = (const float*)d_in[0];
    const float* proj_in_w = (const float*)d_in[1];
    const float* proj_in_b = (const float*)d_in[2];
    const float* hk_dw_w   = (const float*)d_in[3];
    const float* hk_dw_b   = (const float*)d_in[4];
    const float* hk_pw_w   = (const float*)d_in[5];
    const float* hk_pw_b   = (const float*)d_in[6];
    const float* vk_dw_w   = (const float*)d_in[7];
    const float* vk_dw_b   = (const float*)d_in[8];
    const float* vk_pw_w   = (const float*)d_in[9];
    const float* vk_pw_b   = (const float*)d_in[10];
    const float* cb_w1     = (const float*)d_in[11];
    const float* cb_b1     = (const float*)d_in[12];
    const float* cb_w2     = (const float*)d_in[13];
    const float* cb_b2     = (const float*)d_in[14];
    const float* proj_out_w= (const float*)d_in[15];
    const float* proj_out_b= (const float*)d_in[16];
    float* out = (float*)d_out;

    float *p_h, *p_mid, *p_xconv, *p_dw, *p_k, *p_attnh, *p_attn, *p_cat;
    float *p_atmean, *p_xcmean, *p_ssig, *p_csig;
    cudaGetSymbolAddress((void**)&p_h,      g_h);
    cudaGetSymbolAddress((void**)&p_mid,    g_mid);
    cudaGetSymbolAddress((void**)&p_xconv,  g_xconv);
    cudaGetSymbolAddress((void**)&p_dw,     g_dw);
    cudaGetSymbolAddress((void**)&p_k,      g_k);
    cudaGetSymbolAddress((void**)&p_attnh,  g_attnh);
    cudaGetSymbolAddress((void**)&p_attn,   g_attn);
    cudaGetSymbolAddress((void**)&p_cat,    g_cat);
    cudaGetSymbolAddress((void**)&p_atmean, g_atmean);
    cudaGetSymbolAddress((void**)&p_xcmean, g_xcmean);
    cudaGetSymbolAddress((void**)&p_ssig,   g_ssig);
    cudaGetSymbolAddress((void**)&p_csig,   g_csig);

    const int N = PP;
    const int elemBlocks = (NB * C2C * PP) / 256;

    // 1) proj_in: h = x @ W^T + b       (M=256,K=256)
    gemm_tc<0><<<dim3(N/128, 4, NB), 256>>>(proj_in_w, proj_in_b, x, p_h,
                                            256, 256, N, (size_t)256*PP, (size_t)256*PP);
    // 2) cb hidden = relu(x1 @ cb_w1^T) (M=64,K=128)
    gemm_tc<1><<<dim3(N/128, 1, NB), 256>>>(cb_w1, cb_b1, p_h, p_mid,
                                            64, 128, N, (size_t)256*PP, (size_t)64*PP);
    // 3) x_conv = mid @ cb_w2^T         (M=128,K=64)
    gemm_tc<0><<<dim3(N/128, 2, NB), 256>>>(cb_w2, cb_b2, p_mid, p_xconv,
                                            128, 64, N, (size_t)64*PP, (size_t)C2C*PP);
    // 4) horizontal depthwise on x2 = g_h[:, 128:]
    dwconv_h<<<elemBlocks, 256>>>(p_h + (size_t)C2C*PP, (size_t)256*PP, hk_dw_w, hk_dw_b, p_dw);
    // 5) kh = tanh(dwh @ hk_pw^T)       (M=40,K=128)
    gemm_tc<2><<<dim3(N/128, 1, NB), 256>>>(hk_pw_w, hk_pw_b, p_dw, p_k,
                                            GKC, 128, N, (size_t)C2C*PP, (size_t)GKC*PP);
    // 6) attn_h = fsa(x2, kh, axis=w)
    fsa_h<<<elemBlocks, 256>>>(p_h + (size_t)C2C*PP, (size_t)256*PP, p_k, p_attnh);
    // 7) vertical depthwise on attn_h
    dwconv_v<<<elemBlocks, 256>>>(p_attnh, (size_t)C2C*PP, vk_dw_w, vk_dw_b, p_dw);
    // 8) kv = tanh(dwv @ vk_pw^T)
    gemm_tc<2><<<dim3(N/128, 1, NB), 256>>>(vk_pw_w, vk_pw_b, p_dw, p_k,
                                            GKC, 128, N, (size_t)C2C*PP, (size_t)GKC*PP);
    // 9) attn = fsa(attn_h, kv, axis=h)
    fsa_v<<<elemBlocks, 256>>>(p_attnh, (size_t)C2C*PP, p_k, p_attn);
    // 10) at_mean[b,c]
    reduce_mean_p<<<NB*C2C, 256>>>(p_attn, p_atmean);
    // 11) xc_mean[b,p]
    mean_c<<<(NB*PP)/256, 256>>>(p_xconv, p_xcmean);
    // 12) s_sig[b,p]
    ssig_kernel<<<dim3(PP/256, NB), 256>>>(p_xconv, p_atmean, p_ssig);
    // 13) c_sig[b,c]
    csig_kernel<<<NB*C2C, 256>>>(p_attn, p_xcmean, p_csig);
    // 14) concat with gates
    cat_kernel<<<(NB*256*PP)/256, 256>>>(p_xconv, p_attn, p_ssig, p_csig, p_cat);
    // 15) proj_out -> d_out
    gemm_tc<0><<<dim3(N/128, 4, NB), 256>>>(proj_out_w, proj_out_b, p_cat, out,
                                            256, 256, N, (size_t)256*PP, (size_t)256*PP);
}

// round 3
// speedup vs baseline: 2.0015x; 1.5788x over previous
#include <cuda_runtime.h>
#include <math.h>
#include <stdint.h>

#define NB 4
#define C2C 128
#define HH 128
#define WW 128
#define PP (HH*WW)          // 16384
#define GKC 40

// ---------------- scratch -----------------------------------------------------
__device__ float g_h[(size_t)NB*256*PP];
__device__ float g_mid[(size_t)NB*64*PP];
__device__ float g_xconv[(size_t)NB*C2C*PP];
__device__ float g_dw[(size_t)NB*C2C*PP];
__device__ float g_k[(size_t)NB*GKC*PP];
__device__ float g_attnh[(size_t)NB*C2C*PP];
__device__ float g_attn[(size_t)NB*C2C*PP];
__device__ float g_atmean[NB*C2C];
__device__ float g_xcmean[NB*PP];
__device__ float g_ssig[NB*PP];
__device__ float g_csig[NB*C2C];

// ---------------- tf32 helpers -------------------------------------------------
__device__ __forceinline__ uint32_t f2tf32(float x) {
    uint32_t u;
    asm("cvt.rna.tf32.f32 %0, %1;" : "=r"(u) : "f"(x));
    return u;
}
__device__ __forceinline__ void mma_tf32(float c[4], const uint32_t a[4], const uint32_t b[2]) {
    asm volatile(
        "mma.sync.aligned.m16n8k8.row.col.f32.tf32.tf32.f32 "
        "{%0,%1,%2,%3}, {%4,%5,%6,%7}, {%8,%9}, {%0,%1,%2,%3};\n"
        : "+f"(c[0]), "+f"(c[1]), "+f"(c[2]), "+f"(c[3])
        : "r"(a[0]), "r"(a[1]), "r"(a[2]), "r"(a[3]), "r"(b[0]), "r"(b[1]));
}

// ---------------- tf32 GEMM: C[b] = act(A * B[b] + bias) -----------------------
// Tile 128(M) x 128(N), BK=32, 512 threads (16 warps, 4x4), warp tile 32x32.
// GATE=1: B is built on the fly: rows 0..127 = xconv*ssig, rows 128..255 = attn*csig.
template<int ACT, int GATE>
__global__ __launch_bounds__(512) void gemm_tc(
    const float* __restrict__ A, const float* __restrict__ bias,
    const float* __restrict__ Bm, float* __restrict__ Cm,
    int M, int K, int N, size_t sB, size_t sC,
    const float* __restrict__ gAtt, const float* __restrict__ gSs,
    const float* __restrict__ gCs)
{
    __shared__ uint32_t As[128][36];   // [m][k], stride 36 -> conflict-free frags
    __shared__ uint32_t Bs[32][136];   // [k][n], stride 136 -> conflict-free frags

    const int bz = blockIdx.z;
    const float* Bp = Bm + (size_t)bz * sB;
    float*       Cp = Cm + (size_t)bz * sC;
    const float* attB = GATE ? (gAtt + (size_t)bz * C2C * PP) : nullptr;
    const float* ssB  = GATE ? (gSs  + (size_t)bz * PP)       : nullptr;
    const float* csB  = GATE ? (gCs  + (size_t)bz * C2C)      : nullptr;

    const int m0 = blockIdx.y * 128, n0 = blockIdx.x * 128;
    const int tid  = threadIdx.x;
    const int lane = tid & 31, warp = tid >> 5;
    const int wm = warp & 3, wn = warp >> 2;
    const int g = lane >> 2, tig = lane & 3;

    const int aRow = tid >> 3, aCol = (tid & 7) << 2;   // A: 2 passes of 64 rows
    const int bRow = tid >> 5, bCol = (tid & 31) << 2;  // B: 2 passes of 16 rows

    float4 ra[2], rb[2];

    auto loadA = [&](int k0) {
#pragma unroll
        for (int i = 0; i < 2; i++) {
            int r = m0 + aRow + i * 64;
            ra[i] = (r < M) ? *(const float4*)(A + (size_t)r * K + k0 + aCol)
                            : make_float4(0.f, 0.f, 0.f, 0.f);
        }
    };
    auto loadB = [&](int k0) {
#pragma unroll
        for (int i = 0; i < 2; i++) {
            int r = k0 + bRow + i * 16;
            if (!GATE) {
                rb[i] = *(const float4*)(Bp + (size_t)r * N + n0 + bCol);
            } else {
                int col = n0 + bCol;
                if (r < C2C) {
                    float4 xv = *(const float4*)(Bp + (size_t)r * PP + col);
                    float4 sv = *(const float4*)(ssB + col);
                    rb[i] = make_float4(xv.x * sv.x, xv.y * sv.y, xv.z * sv.z, xv.w * sv.w);
                } else {
                    float4 av = *(const float4*)(attB + (size_t)(r - C2C) * PP + col);
                    float cs = csB[r - C2C];
                    rb[i] = make_float4(av.x * cs, av.y * cs, av.z * cs, av.w * cs);
                }
            }
        }
    };
    auto stsAB = [&]() {
#pragma unroll
        for (int i = 0; i < 2; i++) {
            uint4 ua = make_uint4(f2tf32(ra[i].x), f2tf32(ra[i].y), f2tf32(ra[i].z), f2tf32(ra[i].w));
            *(uint4*)&As[aRow + i * 64][aCol] = ua;
            uint4 ub = make_uint4(f2tf32(rb[i].x), f2tf32(rb[i].y), f2tf32(rb[i].z), f2tf32(rb[i].w));
            *(uint4*)&Bs[bRow + i * 16][bCol] = ub;
        }
    };

    float acc[2][4][4];
#pragma unroll
    for (int mi = 0; mi < 2; mi++)
#pragma unroll
        for (int ni = 0; ni < 4; ni++)
#pragma unroll
            for (int r = 0; r < 4; r++) acc[mi][ni][r] = 0.f;

    loadA(0); loadB(0);

    for (int k0 = 0; k0 < K; k0 += 32) {
        stsAB();
        __syncthreads();
        if (k0 + 32 < K) { loadA(k0 + 32); loadB(k0 + 32); }

#pragma unroll
        for (int kk = 0; kk < 4; kk++) {
            const int kb = kk * 8;
            uint32_t a[2][4];
#pragma unroll
            for (int mi = 0; mi < 2; mi++) {
                int m = wm * 32 + mi * 16 + g;
                a[mi][0] = As[m][kb + tig];
                a[mi][1] = As[m + 8][kb + tig];
                a[mi][2] = As[m][kb + tig + 4];
                a[mi][3] = As[m + 8][kb + tig + 4];
            }
            uint32_t b[4][2];
#pragma unroll
            for (int ni = 0; ni < 4; ni++) {
                int n = wn * 32 + ni * 8 + g;
                b[ni][0] = Bs[kb + tig][n];
                b[ni][1] = Bs[kb + tig + 4][n];
            }
#pragma unroll
            for (int mi = 0; mi < 2; mi++)
#pragma unroll
                for (int ni = 0; ni < 4; ni++)
                    mma_tf32(acc[mi][ni], a[mi], b[ni]);
        }
        __syncthreads();
    }

#pragma unroll
    for (int mi = 0; mi < 2; mi++) {
        int row_lo = m0 + wm * 32 + mi * 16 + g;
        int row_hi = row_lo + 8;
        float blo = (row_lo < M) ? bias[row_lo] : 0.f;
        float bhi = (row_hi < M) ? bias[row_hi] : 0.f;
#pragma unroll
        for (int ni = 0; ni < 4; ni++) {
            int col = n0 + wn * 32 + ni * 8 + tig * 2;
            float v0 = acc[mi][ni][0] + blo, v1 = acc[mi][ni][1] + blo;
            float v2 = acc[mi][ni][2] + bhi, v3 = acc[mi][ni][3] + bhi;
            if (ACT == 1) { v0 = fmaxf(v0, 0.f); v1 = fmaxf(v1, 0.f);
                            v2 = fmaxf(v2, 0.f); v3 = fmaxf(v3, 0.f); }
            if (ACT == 2) { v0 = tanhf(v0); v1 = tanhf(v1);
                            v2 = tanhf(v2); v3 = tanhf(v3); }
            if (row_lo < M) *(float2*)(Cp + (size_t)row_lo * N + col) = make_float2(v0, v1);
            if (row_hi < M) *(float2*)(Cp + (size_t)row_hi * N + col) = make_float2(v2, v3);
        }
    }
}

// ---------------- depthwise 1x7 horizontal, 4 outputs/thread -------------------
__global__ void dwconv_h4(const float* __restrict__ x, size_t sX,
                          const float* __restrict__ w7, const float* __restrict__ bias,
                          float* __restrict__ y)
{
    int idx = blockIdx.x * 256 + threadIdx.x;
    if (idx >= NB * C2C * HH * (WW / 4)) return;
    int w4 = (idx & 31) << 2;
    int row = idx >> 5;
    int h = row % HH, c = (row / HH) % C2C, b = row / (HH * C2C);
    const float* xr = x + (size_t)b * sX + (size_t)c * PP + h * WW;
    float v[10];
    if (w4 >= 4 && w4 <= WW - 8) {
#pragma unroll
        for (int t = 0; t < 10; t++) v[t] = xr[w4 - 3 + t];
    } else {
#pragma unroll
        for (int t = 0; t < 10; t++) {
            int wi = w4 - 3 + t;
            v[t] = (wi >= 0 && wi < WW) ? xr[wi] : 0.f;
        }
    }
    float bw = bias[c];
    const float* wc = w7 + c * 7;
    float o[4];
#pragma unroll
    for (int i = 0; i < 4; i++) {
        float s = bw;
#pragma unroll
        for (int j = 0; j < 7; j++) s = fmaf(v[i + j], wc[j], s);
        o[i] = s;
    }
    *(float4*)(y + ((size_t)b * C2C + c) * PP + h * WW + w4) = make_float4(o[0], o[1], o[2], o[3]);
}

// ---------------- depthwise 7x1 vertical, 4 outputs/thread ---------------------
__global__ void dwconv_v4(const float* __restrict__ x, size_t sX,
                          const float* __restrict__ w7, const float* __restrict__ bias,
                          float* __restrict__ y)
{
    int idx = blockIdx.x * 256 + threadIdx.x;
    if (idx >= NB * C2C * (HH / 4) * WW) return;
    int w = idx % WW;
    int h4 = ((idx / WW) & 31) << 2;
    int c = (idx / (WW * 32)) % C2C;
    int b = idx / (WW * 32 * C2C);
    const float* xc = x + (size_t)b * sX + (size_t)c * PP;
    float v[10];
#pragma unroll
    for (int t = 0; t < 10; t++) {
        int hi = h4 - 3 + t;
        v[t] = (hi >= 0 && hi < HH) ? xc[hi * WW + w] : 0.f;
    }
    float bw = bias[c];
    const float* wc = w7 + c * 7;
    float* yb = y + ((size_t)b * C2C + c) * PP + h4 * WW + w;
#pragma unroll
    for (int i = 0; i < 4; i++) {
        float s = bw;
#pragma unroll
        for (int j = 0; j < 7; j++) s = fmaf(v[i + j], wc[j], s);
        yb[i * WW] = s;
    }
}

// ---------------- FSA horizontal, 4 outputs/thread -----------------------------
__global__ void fsa_h4(const float* __restrict__ x, size_t sX,
                       const float* __restrict__ kern, float* __restrict__ out)
{
    int idx = blockIdx.x * 256 + threadIdx.x;
    if (idx >= NB * C2C * HH * (WW / 4)) return;
    int w4 = (idx & 31) << 2;
    int row = idx >> 5;
    int h = row % HH, c = (row / HH) % C2C, b = row / (HH * C2C);
    const float* xr = x + (size_t)b * sX + (size_t)c * PP + h * WW;
    float v[10];
    if (w4 >= 4 && w4 <= WW - 8) {
#pragma unroll
        for (int t = 0; t < 10; t++) v[t] = xr[w4 - 3 + t];
    } else {
#pragma unroll
        for (int t = 0; t < 10; t++) {
            int wi = w4 - 3 + t;
            v[t] = (wi >= 0 && wi < WW) ? xr[wi] : 0.f;
        }
    }
    const float* kb_ = kern + ((size_t)b * GKC + (size_t)(c >> 4) * 5) * PP + h * WW + w4;
    float4 k0 = *(const float4*)(kb_);
    float4 k1 = *(const float4*)(kb_ + PP);
    float4 k2 = *(const float4*)(kb_ + 2 * PP);
    float4 k3 = *(const float4*)(kb_ + 3 * PP);
    float4 k4 = *(const float4*)(kb_ + 4 * PP);
    float K0[4] = {k0.x, k0.y, k0.z, k0.w};
    float K1[4] = {k1.x, k1.y, k1.z, k1.w};
    float K2[4] = {k2.x, k2.y, k2.z, k2.w};
    float K3[4] = {k3.x, k3.y, k3.z, k3.w};
    float K4[4] = {k4.x, k4.y, k4.z, k4.w};
    float o[4];
#pragma unroll
    for (int i = 0; i < 4; i++) {
        float t0 = (v[i] + v[i + 1]) * 0.5f;
        float t4 = (v[i + 5] + v[i + 6]) * 0.5f;
        float s = t0 * K0[i];
        s = fmaf(v[i + 2], K1[i], s);
        s = fmaf(v[i + 3], K2[i], s);
        s = fmaf(v[i + 4], K3[i], s);
        s = fmaf(t4, K4[i], s);
        o[i] = s;
    }
    *(float4*)(out + ((size_t)b * C2C + c) * PP + h * WW + w4) = make_float4(o[0], o[1], o[2], o[3]);
}

// ---------------- FSA vertical, 4 outputs/thread --------------------------------
__global__ void fsa_v4(const float* __restrict__ x, size_t sX,
                       const float* __restrict__ kern, float* __restrict__ out)
{
    int idx = blockIdx.x * 256 + threadIdx.x;
    if (idx >= NB * C2C * (HH / 4) * WW) return;
    int w = idx % WW;
    int h4 = ((idx / WW) & 31) << 2;
    int c = (idx / (WW * 32)) % C2C;
    int b = idx / (WW * 32 * C2C);
    const float* xc = x + (size_t)b * sX + (size_t)c * PP;
    float v[10];
#pragma unroll
    for (int t = 0; t < 10; t++) {
        int hi = h4 - 3 + t;
        v[t] = (hi >= 0 && hi < HH) ? xc[hi * WW + w] : 0.f;
    }
    const float* kb_ = kern + ((size_t)b * GKC + (size_t)(c >> 4) * 5) * PP + h4 * WW + w;
    float* ob = out + ((size_t)b * C2C + c) * PP + h4 * WW + w;
#pragma unroll
    for (int i = 0; i < 4; i++) {
        float t0 = (v[i] + v[i + 1]) * 0.5f;
        float t4 = (v[i + 5] + v[i + 6]) * 0.5f;
        float s = t0 * kb_[i * WW];
        s = fmaf(v[i + 2], kb_[PP + i * WW], s);
        s = fmaf(v[i + 3], kb_[2 * PP + i * WW], s);
        s = fmaf(v[i + 4], kb_[3 * PP + i * WW], s);
        s = fmaf(t4, kb_[4 * PP + i * WW], s);
        ob[i * WW] = s;
    }
}

// ---------------- reductions / gating -------------------------------------------
__global__ void reduce_mean_p(const float* __restrict__ x, float* __restrict__ out)
{
    int bc = blockIdx.x;
    const float* xr = x + (size_t)bc * PP;
    float s = 0.f;
    for (int i = threadIdx.x; i < PP; i += 256) s += xr[i];
    __shared__ float sm[256];
    sm[threadIdx.x] = s; __syncthreads();
    for (int st = 128; st > 0; st >>= 1) {
        if (threadIdx.x < st) sm[threadIdx.x] += sm[threadIdx.x + st];
        __syncthreads();
    }
    if (threadIdx.x == 0) out[bc] = sm[0] * (1.f / PP);
}

__global__ void mean_c(const float* __restrict__ x, float* __restrict__ out)
{
    int idx = blockIdx.x * 256 + threadIdx.x;
    if (idx >= NB * PP) return;
    int p = idx % PP, b = idx / PP;
    const float* xr = x + (size_t)b * C2C * PP + p;
    float s = 0.f;
#pragma unroll 8
    for (int c = 0; c < C2C; c++) s += xr[(size_t)c * PP];
    out[idx] = s * (1.f / C2C);
}

__global__ void ssig_kernel(const float* __restrict__ xconv,
                            const float* __restrict__ atmean,
                            float* __restrict__ out)
{
    int b = blockIdx.y;
    int p = blockIdx.x * 256 + threadIdx.x;
    __shared__ float am[C2C];
    if (threadIdx.x < C2C) am[threadIdx.x] = atmean[b * C2C + threadIdx.x];
    __syncthreads();
    const float* xr = xconv + (size_t)b * C2C * PP + p;
    float s = 0.f;
#pragma unroll 8
    for (int c = 0; c < C2C; c++) s = fmaf(am[c], xr[(size_t)c * PP], s);
    s *= (1.f / C2C);
    out[b * PP + p] = 1.f / (1.f + expf(-s));
}

__global__ void csig_kernel(const float* __restrict__ attn,
                            const float* __restrict__ xcmean,
                            float* __restrict__ out)
{
    int bc = blockIdx.x;
    int b = bc / C2C;
    const float* ar = attn + (size_t)bc * PP;
    const float* xm = xcmean + (size_t)b * PP;
    float s = 0.f;
    for (int i = threadIdx.x; i < PP; i += 256) s = fmaf(ar[i], xm[i], s);
    __shared__ float sm[256];
    sm[threadIdx.x] = s; __syncthreads();
    for (int st = 128; st > 0; st >>= 1) {
        if (threadIdx.x < st) sm[threadIdx.x] += sm[threadIdx.x + st];
        __syncthreads();
    }
    if (threadIdx.x == 0) {
        float v = sm[0] * (1.f / PP);
        out[bc] = 1.f / (1.f + expf(-v));
    }
}

// ---------------- host orchestration --------------------------------------------
extern "C" void kernel_launch(void* const* d_in, const int* in_sizes, int n_in,
                              void* d_out, int out_size)
{
    const float* x         = (const float*)d_in[0];
    const float* proj_in_w = (const float*)d_in[1];
    const float* proj_in_b = (const float*)d_in[2];
    const float* hk_dw_w   = (const float*)d_in[3];
    const float* hk_dw_b   = (const float*)d_in[4];
    const float* hk_pw_w   = (const float*)d_in[5];
    const float* hk_pw_b   = (const float*)d_in[6];
    const float* vk_dw_w   = (const float*)d_in[7];
    const float* vk_dw_b   = (const float*)d_in[8];
    const float* vk_pw_w   = (const float*)d_in[9];
    const float* vk_pw_b   = (const float*)d_in[10];
    const float* cb_w1     = (const float*)d_in[11];
    const float* cb_b1     = (const float*)d_in[12];
    const float* cb_w2     = (const float*)d_in[13];
    const float* cb_b2     = (const float*)d_in[14];
    const float* proj_out_w= (const float*)d_in[15];
    const float* proj_out_b= (const float*)d_in[16];
    float* out = (float*)d_out;

    float *p_h, *p_mid, *p_xconv, *p_dw, *p_k, *p_attnh, *p_attn;
    float *p_atmean, *p_xcmean, *p_ssig, *p_csig;
    cudaGetSymbolAddress((void**)&p_h,      g_h);
    cudaGetSymbolAddress((void**)&p_mid,    g_mid);
    cudaGetSymbolAddress((void**)&p_xconv,  g_xconv);
    cudaGetSymbolAddress((void**)&p_dw,     g_dw);
    cudaGetSymbolAddress((void**)&p_k,      g_k);
    cudaGetSymbolAddress((void**)&p_attnh,  g_attnh);
    cudaGetSymbolAddress((void**)&p_attn,   g_attn);
    cudaGetSymbolAddress((void**)&p_atmean, g_atmean);
    cudaGetSymbolAddress((void**)&p_xcmean, g_xcmean);
    cudaGetSymbolAddress((void**)&p_ssig,   g_ssig);
    cudaGetSymbolAddress((void**)&p_csig,   g_csig);

    const int N = PP;
    const int eb4 = (NB * C2C * PP / 4) / 256;   // 8192 blocks for 4-wide kernels

    // 1) proj_in: h = W x + b (M=256,K=256)
    gemm_tc<0,0><<<dim3(N/128, 2, NB), 512>>>(proj_in_w, proj_in_b, x, p_h,
        256, 256, N, (size_t)256*PP, (size_t)256*PP, nullptr, nullptr, nullptr);
    // 2) cb hidden = relu(cb_w1 x1) (M=64,K=128)
    gemm_tc<1,0><<<dim3(N/128, 1, NB), 512>>>(cb_w1, cb_b1, p_h, p_mid,
        64, 128, N, (size_t)256*PP, (size_t)64*PP, nullptr, nullptr, nullptr);
    // 3) x_conv (M=128,K=64)
    gemm_tc<0,0><<<dim3(N/128, 1, NB), 512>>>(cb_w2, cb_b2, p_mid, p_xconv,
        128, 64, N, (size_t)64*PP, (size_t)C2C*PP, nullptr, nullptr, nullptr);
    // 4) horizontal depthwise on x2
    dwconv_h4<<<eb4, 256>>>(p_h + (size_t)C2C*PP, (size_t)256*PP, hk_dw_w, hk_dw_b, p_dw);
    // 5) kh = tanh(hk_pw dwh) (M=40,K=128)
    gemm_tc<2,0><<<dim3(N/128, 1, NB), 512>>>(hk_pw_w, hk_pw_b, p_dw, p_k,
        GKC, 128, N, (size_t)C2C*PP, (size_t)GKC*PP, nullptr, nullptr, nullptr);
    // 6) attn_h
    fsa_h4<<<eb4, 256>>>(p_h + (size_t)C2C*PP, (size_t)256*PP, p_k, p_attnh);
    // 7) vertical depthwise
    dwconv_v4<<<eb4, 256>>>(p_attnh, (size_t)C2C*PP, vk_dw_w, vk_dw_b, p_dw);
    // 8) kv
    gemm_tc<2,0><<<dim3(N/128, 1, NB), 512>>>(vk_pw_w, vk_pw_b, p_dw, p_k,
        GKC, 128, N, (size_t)C2C*PP, (size_t)GKC*PP, nullptr, nullptr, nullptr);
    // 9) attn
    fsa_v4<<<eb4, 256>>>(p_attnh, (size_t)C2C*PP, p_k, p_attn);
    // 10-13) gates
    reduce_mean_p<<<NB*C2C, 256>>>(p_attn, p_atmean);
    mean_c<<<(NB*PP)/256, 256>>>(p_xconv, p_xcmean);
    ssig_kernel<<<dim3(PP/256, NB), 256>>>(p_xconv, p_atmean, p_ssig);
    csig_kernel<<<NB*C2C, 256>>>(p_attn, p_xcmean, p_csig);
    // 14) proj_out with fused gating/concat (M=256,K=256)
    gemm_tc<0,1><<<dim3(N/128, 2, NB), 512>>>(proj_out_w, proj_out_b, p_xconv, out,
        256, 256, N, (size_t)C2C*PP, (size_t)256*PP, p_attn, p_ssig, p_csig);
}

// round 4
// speedup vs baseline: 2.0779x; 1.0382x over previous
#include <cuda_runtime.h>
#include <math.h>
#include <stdint.h>

#define NB 4
#define C2C 128
#define HH 128
#define WW 128
#define PP (HH*WW)          // 16384
#define GKC 40

// GEMM tile config
#define BM 128
#define BN 256
#define BK 32
#define AS_STRIDE 36
#define BS_STRIDE 264
#define AS_WORDS (BM*AS_STRIDE)          // 4608
#define BS_WORDS (BK*BS_STRIDE)          // 8448
#define SMEM_WORDS (2*(AS_WORDS+BS_WORDS))
#define SMEM_BYTES (SMEM_WORDS*4)        // 104448

// ---------------- scratch -----------------------------------------------------
__device__ float g_h[(size_t)NB*256*PP];
__device__ float g_mid[(size_t)NB*64*PP];
__device__ float g_xconv[(size_t)NB*C2C*PP];
__device__ float g_dw[(size_t)NB*C2C*PP];
__device__ float g_k[(size_t)NB*GKC*PP];
__device__ float g_attnh[(size_t)NB*C2C*PP];
__device__ float g_attn[(size_t)NB*C2C*PP];
__device__ float g_atmean[NB*C2C];
__device__ float g_xcmean[NB*PP];
__device__ float g_ssig[NB*PP];
__device__ float g_csig[NB*C2C];

// ---------------- tf32 helpers -------------------------------------------------
__device__ __forceinline__ uint32_t f2tf32(float x) {
    uint32_t u;
    asm("cvt.rna.tf32.f32 %0, %1;" : "=r"(u) : "f"(x));
    return u;
}
__device__ __forceinline__ void mma_tf32(float c[4], const uint32_t a[4], const uint32_t b[2]) {
    asm volatile(
        "mma.sync.aligned.m16n8k8.row.col.f32.tf32.tf32.f32 "
        "{%0,%1,%2,%3}, {%4,%5,%6,%7}, {%8,%9}, {%0,%1,%2,%3};\n"
        : "+f"(c[0]), "+f"(c[1]), "+f"(c[2]), "+f"(c[3])
        : "r"(a[0]), "r"(a[1]), "r"(a[2]), "r"(a[3]), "r"(b[0]), "r"(b[1]));
}

// ---------------- tf32 GEMM: C[b] = act(A * B[b] + bias) -----------------------
// Tile 128M x 256N, BK=32, 512 threads (16 warps, 4m x 4n), warp tile 32x64.
// Two-stage smem double buffer, one __syncthreads per k-tile.
// GATE=1: B rows 0..127 = xconv*ssig, rows 128..255 = attn*csig (built on the fly).
template<int ACT, int GATE>
__global__ __launch_bounds__(512) void gemm_tc(
    const float* __restrict__ A, const float* __restrict__ bias,
    const float* __restrict__ Bm, float* __restrict__ Cm,
    int M, int K, int N, size_t sB, size_t sC,
    const float* __restrict__ gAtt, const float* __restrict__ gSs,
    const float* __restrict__ gCs)
{
    extern __shared__ uint32_t smw[];
    uint32_t* AsB[2] = { smw,              smw + AS_WORDS };
    uint32_t* BsB[2] = { smw + 2*AS_WORDS, smw + 2*AS_WORDS + BS_WORDS };

    const int bz = blockIdx.z;
    const float* Bp = Bm + (size_t)bz * sB;
    float*       Cp = Cm + (size_t)bz * sC;
    const float* attB = GATE ? (gAtt + (size_t)bz * C2C * PP) : nullptr;
    const float* ssB  = GATE ? (gSs  + (size_t)bz * PP)       : nullptr;
    const float* csB  = GATE ? (gCs  + (size_t)bz * C2C)      : nullptr;

    const int m0 = blockIdx.y * BM, n0 = blockIdx.x * BN;
    const int tid  = threadIdx.x;
    const int lane = tid & 31, warp = tid >> 5;
    const int wm = warp & 3, wn = warp >> 2;
    const int g = lane >> 2, tig = lane & 3;

    const int aRow = tid >> 3, aCol = (tid & 7) << 2;   // 2 passes of 64 rows
    const int bRow = tid >> 6, bCol = (tid & 63) << 2;  // 4 passes of 8 rows

    float4 ra[2], rb[4];

    auto loadA = [&](int k0) {
#pragma unroll
        for (int i = 0; i < 2; i++) {
            int r = m0 + aRow + i * 64;
            ra[i] = (r < M) ? *(const float4*)(A + (size_t)r * K + k0 + aCol)
                            : make_float4(0.f, 0.f, 0.f, 0.f);
        }
    };
    auto loadB = [&](int k0) {
#pragma unroll
        for (int i = 0; i < 4; i++) {
            int r = k0 + bRow + i * 8;
            if (!GATE) {
                rb[i] = *(const float4*)(Bp + (size_t)r * N + n0 + bCol);
            } else {
                int col = n0 + bCol;
                if (r < C2C) {
                    float4 xv = *(const float4*)(Bp + (size_t)r * PP + col);
                    float4 sv = *(const float4*)(ssB + col);
                    rb[i] = make_float4(xv.x * sv.x, xv.y * sv.y, xv.z * sv.z, xv.w * sv.w);
                } else {
                    float4 av = *(const float4*)(attB + (size_t)(r - C2C) * PP + col);
                    float cs = csB[r - C2C];
                    rb[i] = make_float4(av.x * cs, av.y * cs, av.z * cs, av.w * cs);
                }
            }
        }
    };
    auto stsAB = [&](int buf) {
        uint32_t* As = AsB[buf];
        uint32_t* Bs = BsB[buf];
#pragma unroll
        for (int i = 0; i < 2; i++) {
            uint4 ua = make_uint4(f2tf32(ra[i].x), f2tf32(ra[i].y), f2tf32(ra[i].z), f2tf32(ra[i].w));
            *(uint4*)&As[(aRow + i * 64) * AS_STRIDE + aCol] = ua;
        }
#pragma unroll
        for (int i = 0; i < 4; i++) {
            uint4 ub = make_uint4(f2tf32(rb[i].x), f2tf32(rb[i].y), f2tf32(rb[i].z), f2tf32(rb[i].w));
            *(uint4*)&Bs[(bRow + i * 8) * BS_STRIDE + bCol] = ub;
        }
    };

    float acc[2][8][4];
#pragma unroll
    for (int mi = 0; mi < 2; mi++)
#pragma unroll
        for (int ni = 0; ni < 8; ni++)
#pragma unroll
            for (int r = 0; r < 4; r++) acc[mi][ni][r] = 0.f;

    loadA(0); loadB(0);
    stsAB(0);
    __syncthreads();

    int buf = 0;
    for (int k0 = 0;;) {
        const int knext = k0 + BK;
        if (knext < K) { loadA(knext); loadB(knext); }

        const uint32_t* As = AsB[buf];
        const uint32_t* Bs = BsB[buf];
#pragma unroll
        for (int kk = 0; kk < 4; kk++) {
            const int kb = kk * 8;
            uint32_t a[2][4];
#pragma unroll
            for (int mi = 0; mi < 2; mi++) {
                int m = wm * 32 + mi * 16 + g;
                a[mi][0] = As[m * AS_STRIDE + kb + tig];
                a[mi][1] = As[(m + 8) * AS_STRIDE + kb + tig];
                a[mi][2] = As[m * AS_STRIDE + kb + tig + 4];
                a[mi][3] = As[(m + 8) * AS_STRIDE + kb + tig + 4];
            }
            uint32_t b[8][2];
#pragma unroll
            for (int ni = 0; ni < 8; ni++) {
                int n = wn * 64 + ni * 8 + g;
                b[ni][0] = Bs[(kb + tig) * BS_STRIDE + n];
                b[ni][1] = Bs[(kb + tig + 4) * BS_STRIDE + n];
            }
#pragma unroll
            for (int mi = 0; mi < 2; mi++)
#pragma unroll
                for (int ni = 0; ni < 8; ni++)
                    mma_tf32(acc[mi][ni], a[mi], b[ni]);
        }

        if (knext >= K) break;
        stsAB(buf ^ 1);
        __syncthreads();
        buf ^= 1;
        k0 = knext;
    }

#pragma unroll
    for (int mi = 0; mi < 2; mi++) {
        int row_lo = m0 + wm * 32 + mi * 16 + g;
        int row_hi = row_lo + 8;
        float blo = (row_lo < M) ? bias[row_lo] : 0.f;
        float bhi = (row_hi < M) ? bias[row_hi] : 0.f;
#pragma unroll
        for (int ni = 0; ni < 8; ni++) {
            int col = n0 + wn * 64 + ni * 8 + tig * 2;
            float v0 = acc[mi][ni][0] + blo, v1 = acc[mi][ni][1] + blo;
            float v2 = acc[mi][ni][2] + bhi, v3 = acc[mi][ni][3] + bhi;
            if (ACT == 1) { v0 = fmaxf(v0, 0.f); v1 = fmaxf(v1, 0.f);
                            v2 = fmaxf(v2, 0.f); v3 = fmaxf(v3, 0.f); }
            if (ACT == 2) { v0 = tanhf(v0); v1 = tanhf(v1);
                            v2 = tanhf(v2); v3 = tanhf(v3); }
            if (row_lo < M) *(float2*)(Cp + (size_t)row_lo * N + col) = make_float2(v0, v1);
            if (row_hi < M) *(float2*)(Cp + (size_t)row_hi * N + col) = make_float2(v2, v3);
        }
    }
}

// ---------------- depthwise 1x7 horizontal, 4 outputs/thread -------------------
__global__ void dwconv_h4(const float* __restrict__ x, size_t sX,
                          const float* __restrict__ w7, const float* __restrict__ bias,
                          float* __restrict__ y)
{
    int idx = blockIdx.x * 256 + threadIdx.x;
    if (idx >= NB * C2C * HH * (WW / 4)) return;
    int w4 = (idx & 31) << 2;
    int row = idx >> 5;
    int h = row % HH, c = (row / HH) % C2C, b = row / (HH * C2C);
    const float* xr = x + (size_t)b * sX + (size_t)c * PP + h * WW;
    float v[10];
    if (w4 >= 4 && w4 <= WW - 8) {
#pragma unroll
        for (int t = 0; t < 10; t++) v[t] = xr[w4 - 3 + t];
    } else {
#pragma unroll
        for (int t = 0; t < 10; t++) {
            int wi = w4 - 3 + t;
            v[t] = (wi >= 0 && wi < WW) ? xr[wi] : 0.f;
        }
    }
    float bw = bias[c];
    const float* wc = w7 + c * 7;
    float o[4];
#pragma unroll
    for (int i = 0; i < 4; i++) {
        float s = bw;
#pragma unroll
        for (int j = 0; j < 7; j++) s = fmaf(v[i + j], wc[j], s);
        o[i] = s;
    }
    *(float4*)(y + ((size_t)b * C2C + c) * PP + h * WW + w4) = make_float4(o[0], o[1], o[2], o[3]);
}

// ---------------- depthwise 7x1 vertical, 4 outputs/thread ---------------------
__global__ void dwconv_v4(const float* __restrict__ x, size_t sX,
                          const float* __restrict__ w7, const float* __restrict__ bias,
                          float* __restrict__ y)
{
    int idx = blockIdx.x * 256 + threadIdx.x;
    if (idx >= NB * C2C * (HH / 4) * WW) return;
    int w = idx % WW;
    int h4 = ((idx / WW) & 31) << 2;
    int c = (idx / (WW * 32)) % C2C;
    int b = idx / (WW * 32 * C2C);
    const float* xc = x + (size_t)b * sX + (size_t)c * PP;
    float v[10];
#pragma unroll
    for (int t = 0; t < 10; t++) {
        int hi = h4 - 3 + t;
        v[t] = (hi >= 0 && hi < HH) ? xc[hi * WW + w] : 0.f;
    }
    float bw = bias[c];
    const float* wc = w7 + c * 7;
    float* yb = y + ((size_t)b * C2C + c) * PP + h4 * WW + w;
#pragma unroll
    for (int i = 0; i < 4; i++) {
        float s = bw;
#pragma unroll
        for (int j = 0; j < 7; j++) s = fmaf(v[i + j], wc[j], s);
        yb[i * WW] = s;
    }
}

// ---------------- FSA horizontal, 4 outputs/thread -----------------------------
__global__ void fsa_h4(const float* __restrict__ x, size_t sX,
                       const float* __restrict__ kern, float* __restrict__ out)
{
    int idx = blockIdx.x * 256 + threadIdx.x;
    if (idx >= NB * C2C * HH * (WW / 4)) return;
    int w4 = (idx & 31) << 2;
    int row = idx >> 5;
    int h = row % HH, c = (row / HH) % C2C, b = row / (HH * C2C);
    const float* xr = x + (size_t)b * sX + (size_t)c * PP + h * WW;
    float v[10];
    if (w4 >= 4 && w4 <= WW - 8) {
#pragma unroll
        for (int t = 0; t < 10; t++) v[t] = xr[w4 - 3 + t];
    } else {
#pragma unroll
        for (int t = 0; t < 10; t++) {
            int wi = w4 - 3 + t;
            v[t] = (wi >= 0 && wi < WW) ? xr[wi] : 0.f;
        }
    }
    const float* kb_ = kern + ((size_t)b * GKC + (size_t)(c >> 4) * 5) * PP + h * WW + w4;
    float4 k0 = *(const float4*)(kb_);
    float4 k1 = *(const float4*)(kb_ + PP);
    float4 k2 = *(const float4*)(kb_ + 2 * PP);
    float4 k3 = *(const float4*)(kb_ + 3 * PP);
    float4 k4 = *(const float4*)(kb_ + 4 * PP);
    float K0[4] = {k0.x, k0.y, k0.z, k0.w};
    float K1[4] = {k1.x, k1.y, k1.z, k1.w};
    float K2[4] = {k2.x, k2.y, k2.z, k2.w};
    float K3[4] = {k3.x, k3.y, k3.z, k3.w};
    float K4[4] = {k4.x, k4.y, k4.z, k4.w};
    float o[4];
#pragma unroll
    for (int i = 0; i < 4; i++) {
        float t0 = (v[i] + v[i + 1]) * 0.5f;
        float t4 = (v[i + 5] + v[i + 6]) * 0.5f;
        float s = t0 * K0[i];
        s = fmaf(v[i + 2], K1[i], s);
        s = fmaf(v[i + 3], K2[i], s);
        s = fmaf(v[i + 4], K3[i], s);
        s = fmaf(t4, K4[i], s);
        o[i] = s;
    }
    *(float4*)(out + ((size_t)b * C2C + c) * PP + h * WW + w4) = make_float4(o[0], o[1], o[2], o[3]);
}

// ---------------- FSA vertical, 4 outputs/thread --------------------------------
__global__ void fsa_v4(const float* __restrict__ x, size_t sX,
                       const float* __restrict__ kern, float* __restrict__ out)
{
    int idx = blockIdx.x * 256 + threadIdx.x;
    if (idx >= NB * C2C * (HH / 4) * WW) return;
    int w = idx % WW;
    int h4 = ((idx / WW) & 31) << 2;
    int c = (idx / (WW * 32)) % C2C;
    int b = idx / (WW * 32 * C2C);
    const float* xc = x + (size_t)b * sX + (size_t)c * PP;
    float v[10];
#pragma unroll
    for (int t = 0; t < 10; t++) {
        int hi = h4 - 3 + t;
        v[t] = (hi >= 0 && hi < HH) ? xc[hi * WW + w] : 0.f;
    }
    const float* kb_ = kern + ((size_t)b * GKC + (size_t)(c >> 4) * 5) * PP + h4 * WW + w;
    float* ob = out + ((size_t)b * C2C + c) * PP + h4 * WW + w;
#pragma unroll
    for (int i = 0; i < 4; i++) {
        float t0 = (v[i] + v[i + 1]) * 0.5f;
        float t4 = (v[i + 5] + v[i + 6]) * 0.5f;
        float s = t0 * kb_[i * WW];
        s = fmaf(v[i + 2], kb_[PP + i * WW], s);
        s = fmaf(v[i + 3], kb_[2 * PP + i * WW], s);
        s = fmaf(v[i + 4], kb_[3 * PP + i * WW], s);
        s = fmaf(t4, kb_[4 * PP + i * WW], s);
        ob[i * WW] = s;
    }
}

// ---------------- reductions / gating -------------------------------------------
__global__ void reduce_mean_p(const float* __restrict__ x, float* __restrict__ out)
{
    int bc = blockIdx.x;
    const float* xr = x + (size_t)bc * PP;
    float s = 0.f;
    for (int i = threadIdx.x; i < PP; i += 256) s += xr[i];
    __shared__ float sm[256];
    sm[threadIdx.x] = s; __syncthreads();
    for (int st = 128; st > 0; st >>= 1) {
        if (threadIdx.x < st) sm[threadIdx.x] += sm[threadIdx.x + st];
        __syncthreads();
    }
    if (threadIdx.x == 0) out[bc] = sm[0] * (1.f / PP);
}

// fused: s_sig[b,p] = sigmoid(dot(atmean, xconv[:,p])/128), xcmean[b,p] = mean_c(xconv)
__global__ void ssig_xcmean(const float* __restrict__ xconv,
                            const float* __restrict__ atmean,
                            float* __restrict__ ssig, float* __restrict__ xcm)
{
    int b = blockIdx.y;
    int p = blockIdx.x * 256 + threadIdx.x;
    __shared__ float am[C2C];
    if (threadIdx.x < C2C) am[threadIdx.x] = atmean[b * C2C + threadIdx.x];
    __syncthreads();
    const float* xr = xconv + (size_t)b * C2C * PP + p;
    float s = 0.f, m = 0.f;
#pragma unroll 8
    for (int c = 0; c < C2C; c++) {
        float v = xr[(size_t)c * PP];
        s = fmaf(am[c], v, s);
        m += v;
    }
    s *= (1.f / C2C);
    ssig[b * PP + p] = 1.f / (1.f + expf(-s));
    xcm[b * PP + p] = m * (1.f / C2C);
}

__global__ void csig_kernel(const float* __restrict__ attn,
                            const float* __restrict__ xcmean,
                            float* __restrict__ out)
{
    int bc = blockIdx.x;
    int b = bc / C2C;
    const float* ar = attn + (size_t)bc * PP;
    const float* xm = xcmean + (size_t)b * PP;
    float s = 0.f;
    for (int i = threadIdx.x; i < PP; i += 256) s = fmaf(ar[i], xm[i], s);
    __shared__ float sm[256];
    sm[threadIdx.x] = s; __syncthreads();
    for (int st = 128; st > 0; st >>= 1) {
        if (threadIdx.x < st) sm[threadIdx.x] += sm[threadIdx.x + st];
        __syncthreads();
    }
    if (threadIdx.x == 0) {
        float v = sm[0] * (1.f / PP);
        out[bc] = 1.f / (1.f + expf(-v));
    }
}

// ---------------- host orchestration --------------------------------------------
extern "C" void kernel_launch(void* const* d_in, const int* in_sizes, int n_in,
                              void* d_out, int out_size)
{
    const float* x         = (const float*)d_in[0];
    const float* proj_in_w = (const float*)d_in[1];
    const float* proj_in_b = (const float*)d_in[2];
    const float* hk_dw_w   = (const float*)d_in[3];
    const float* hk_dw_b   = (const float*)d_in[4];
    const float* hk_pw_w   = (const float*)d_in[5];
    const float* hk_pw_b   = (const float*)d_in[6];
    const float* vk_dw_w   = (const float*)d_in[7];
    const float* vk_dw_b   = (const float*)d_in[8];
    const float* vk_pw_w   = (const float*)d_in[9];
    const float* vk_pw_b   = (const float*)d_in[10];
    const float* cb_w1     = (const float*)d_in[11];
    const float* cb_b1     = (const float*)d_in[12];
    const float* cb_w2     = (const float*)d_in[13];
    const float* cb_b2     = (const float*)d_in[14];
    const float* proj_out_w= (const float*)d_in[15];
    const float* proj_out_b= (const float*)d_in[16];
    float* out = (float*)d_out;

    static int smem_set = 0;
    if (!smem_set) {
        cudaFuncSetAttribute(gemm_tc<0,0>, cudaFuncAttributeMaxDynamicSharedMemorySize, SMEM_BYTES);
        cudaFuncSetAttribute(gemm_tc<1,0>, cudaFuncAttributeMaxDynamicSharedMemorySize, SMEM_BYTES);
        cudaFuncSetAttribute(gemm_tc<2,0>, cudaFuncAttributeMaxDynamicSharedMemorySize, SMEM_BYTES);
        cudaFuncSetAttribute(gemm_tc<0,1>, cudaFuncAttributeMaxDynamicSharedMemorySize, SMEM_BYTES);
        smem_set = 1;
    }

    float *p_h, *p_mid, *p_xconv, *p_dw, *p_k, *p_attnh, *p_attn;
    float *p_atmean, *p_xcmean, *p_ssig, *p_csig;
    cudaGetSymbolAddress((void**)&p_h,      g_h);
    cudaGetSymbolAddress((void**)&p_mid,    g_mid);
    cudaGetSymbolAddress((void**)&p_xconv,  g_xconv);
    cudaGetSymbolAddress((void**)&p_dw,     g_dw);
    cudaGetSymbolAddress((void**)&p_k,      g_k);
    cudaGetSymbolAddress((void**)&p_attnh,  g_attnh);
    cudaGetSymbolAddress((void**)&p_attn,   g_attn);
    cudaGetSymbolAddress((void**)&p_atmean, g_atmean);
    cudaGetSymbolAddress((void**)&p_xcmean, g_xcmean);
    cudaGetSymbolAddress((void**)&p_ssig,   g_ssig);
    cudaGetSymbolAddress((void**)&p_csig,   g_csig);

    const int N = PP;
    const int eb4 = (NB * C2C * PP / 4) / 256;

    // 1) proj_in (M=256,K=256)
    gemm_tc<0,0><<<dim3(N/BN, 2, NB), 512, SMEM_BYTES>>>(proj_in_w, proj_in_b, x, p_h,
        256, 256, N, (size_t)256*PP, (size_t)256*PP, nullptr, nullptr, nullptr);
    // 2) cb hidden = relu (M=64,K=128)
    gemm_tc<1,0><<<dim3(N/BN, 1, NB), 512, SMEM_BYTES>>>(cb_w1, cb_b1, p_h, p_mid,
        64, 128, N, (size_t)256*PP, (size_t)64*PP, nullptr, nullptr, nullptr);
    // 3) x_conv (M=128,K=64)
    gemm_tc<0,0><<<dim3(N/BN, 1, NB), 512, SMEM_BYTES>>>(cb_w2, cb_b2, p_mid, p_xconv,
        128, 64, N, (size_t)64*PP, (size_t)C2C*PP, nullptr, nullptr, nullptr);
    // 4) horizontal depthwise on x2
    dwconv_h4<<<eb4, 256>>>(p_h + (size_t)C2C*PP, (size_t)256*PP, hk_dw_w, hk_dw_b, p_dw);
    // 5) kh = tanh (M=40,K=128)
    gemm_tc<2,0><<<dim3(N/BN, 1, NB), 512, SMEM_BYTES>>>(hk_pw_w, hk_pw_b, p_dw, p_k,
        GKC, 128, N, (size_t)C2C*PP, (size_t)GKC*PP, nullptr, nullptr, nullptr);
    // 6) attn_h
    fsa_h4<<<eb4, 256>>>(p_h + (size_t)C2C*PP, (size_t)256*PP, p_k, p_attnh);
    // 7) vertical depthwise
    dwconv_v4<<<eb4, 256>>>(p_attnh, (size_t)C2C*PP, vk_dw_w, vk_dw_b, p_dw);
    // 8) kv = tanh (M=40,K=128)
    gemm_tc<2,0><<<dim3(N/BN, 1, NB), 512, SMEM_BYTES>>>(vk_pw_w, vk_pw_b, p_dw, p_k,
        GKC, 128, N, (size_t)C2C*PP, (size_t)GKC*PP, nullptr, nullptr, nullptr);
    // 9) attn
    fsa_v4<<<eb4, 256>>>(p_attnh, (size_t)C2C*PP, p_k, p_attn);
    // 10) at_mean
    reduce_mean_p<<<NB*C2C, 256>>>(p_attn, p_atmean);
    // 11) fused ssig + xcmean
    ssig_xcmean<<<dim3(PP/256, NB), 256>>>(p_xconv, p_atmean, p_ssig, p_xcmean);
    // 12) c_sig
    csig_kernel<<<NB*C2C, 256>>>(p_attn, p_xcmean, p_csig);
    // 13) proj_out with fused gating/concat (M=256,K=256)
    gemm_tc<0,1><<<dim3(N/BN, 2, NB), 512, SMEM_BYTES>>>(proj_out_w, proj_out_b, p_xconv, out,
        256, 256, N, (size_t)C2C*PP, (size_t)256*PP, p_attn, p_ssig, p_csig);
}